// round 1
// baseline (speedup 1.0000x reference)
#include <cuda_runtime.h>
#include <cuda_bf16.h>

#define NB 32
#define WARPS_PER_BLOCK 8
#define THREADS (WARPS_PER_BLOCK * 32)

__device__ __forceinline__ float clamp01(float x) {
    return fminf(fmaxf(x, 0.0f), 1.0f);
}

__global__ __launch_bounds__(THREADS)
void BioTokenMucusSim_kernel(const float* __restrict__ h,
                             const float* __restrict__ W,
                             const float* __restrict__ stim,
                             float* __restrict__ h_out,
                             float* __restrict__ W_out,
                             int n_pairs)
{
    // Per-warp 32x32 W tile, stride 33 (conflict-free rows AND columns)
    __shared__ float wsh[WARPS_PER_BLOCK][NB * 33];

    const int warp = threadIdx.x >> 5;
    const int lane = threadIdx.x & 31;
    const int pair = blockIdx.x * WARPS_PER_BLOCK + warp;
    if (pair >= n_pairs) return;

    const float* Wp = W + (size_t)pair * (NB * NB);
    const float* hp = h + (size_t)pair * (NB * 4);
    float* ws = wsh[warp];

    // ---- Load W tile coalesced: warp reads 128B rows, shared stride 33 ----
    #pragma unroll
    for (int k = 0; k < NB; ++k)
        ws[k * 33 + lane] = Wp[k * NB + lane];

    // ---- Load h row for this lane (one float4 = one EPGL vector) ----
    const float4 hv = ((const float4*)hp)[lane];
    const float s = stim[(size_t)pair * NB + lane];

    __syncwarp();

    // ---- Masked matvec: inflow[i,c] = sum_{j!=i} W[i,j] * h[j,c] ----
    float ifx = 0.f, ify = 0.f, ifz = 0.f, ifw = 0.f, wsum = 0.f;
    #pragma unroll
    for (int j = 0; j < NB; ++j) {
        float wij = ws[lane * 33 + j];
        wij = (j == lane) ? 0.0f : wij;
        const float hx = __shfl_sync(0xffffffffu, hv.x, j);
        const float hy = __shfl_sync(0xffffffffu, hv.y, j);
        const float hz = __shfl_sync(0xffffffffu, hv.z, j);
        const float hw = __shfl_sync(0xffffffffu, hv.w, j);
        ifx += wij * hx;
        ify += wij * hy;
        ifz += wij * hz;
        ifw += wij * hw;
        wsum += wij;
    }
    const float inv = 1.0f / (wsum + 1e-8f);
    const float En = ifx * inv, Pn = ify * inv, Gn = ifz * inv, Ln = ifw * inv;

    // ---- Channel update ----
    const float E = hv.x, P = hv.y, G = hv.z, L = hv.w;
    const float E_new = clamp01(E + 0.3f * s - 0.4f * P - 0.2f * G);
    const float P_new = clamp01(P + 0.5f * s + 0.3f * (Pn - P) - 0.2f * E);
    const float G_new = clamp01(G + 0.4f * E * (1.0f - P) + 0.2f * (Gn - G) - 0.3f * P);
    const float good  = 0.5f * En + 0.5f * Gn;
    const float L_new = clamp01(L + 0.4f * good + 0.3f * (Ln - L) - 0.3f * P);

    const float4 hn = make_float4(E_new, P_new, G_new, L_new);
    ((float4*)(h_out + (size_t)pair * (NB * 4)))[lane] = hn;

    // ---- W update: lane i owns row i; need h_new[j] via shuffle ----
    #pragma unroll
    for (int j = 0; j < NB; ++j) {
        const float jx = __shfl_sync(0xffffffffu, hn.x, j);
        const float jy = __shfl_sync(0xffffffffu, hn.y, j);
        const float jz = __shfl_sync(0xffffffffu, hn.z, j);
        const float jw = __shfl_sync(0xffffffffu, hn.w, j);
        const float dx = hn.x - jx, dy = hn.y - jy;
        const float dz = hn.z - jz, dw = hn.w - jw;
        const float sq = dx * dx + dy * dy + dz * dz + dw * dw;
        const float dist = sqrtf(sq);      // sqrtf(0)=0 matches the where() guard
        const float wij = ws[lane * 33 + j];
        // W_new = W + 0.1*0.5*(Li+Lj)*dist - 0.05*W = 0.95*W + 0.05*(Li+Lj)*dist
        float wn = 0.95f * wij + 0.05f * (hn.w + jw) * dist;
        wn = clamp01(wn);
        if (j == lane) wn = 0.0f;          // (1 - eye)
        ws[lane * 33 + j] = wn;
    }
    __syncwarp();

    // ---- Store W_new coalesced ----
    float* Wo = W_out + (size_t)pair * (NB * NB);
    #pragma unroll
    for (int k = 0; k < NB; ++k)
        Wo[k * NB + lane] = ws[k * 33 + lane];
}

extern "C" void kernel_launch(void* const* d_in, const int* in_sizes, int n_in,
                              void* d_out, int out_size) {
    const float* h    = (const float*)d_in[0];  // [B,S,32,4]
    const float* W    = (const float*)d_in[1];  // [B,S,32,32]
    const float* stim = (const float*)d_in[2];  // [B,S,32]

    const int n_pairs = in_sizes[2] / NB;       // B*S

    float* h_out = (float*)d_out;                       // h_new first
    float* W_out = (float*)d_out + (size_t)in_sizes[0]; // then W_new

    const int blocks = (n_pairs + WARPS_PER_BLOCK - 1) / WARPS_PER_BLOCK;
    BioTokenMucusSim_kernel<<<blocks, THREADS>>>(h, W, stim, h_out, W_out, n_pairs);
}

// round 2
// speedup vs baseline: 1.1154x; 1.1154x over previous
#include <cuda_runtime.h>
#include <cuda_bf16.h>

#define NB 32
#define WPB 8
#define THREADS (WPB * 32)
#define STRIDE 36   // floats per shared row: conflict-free for row-float4 AND col access

__device__ __forceinline__ float clamp01(float x) {
    return fminf(fmaxf(x, 0.0f), 1.0f);
}

__global__ __launch_bounds__(THREADS)
void BioTokenMucusSim_kernel(const float* __restrict__ h,
                             const float* __restrict__ W,
                             const float* __restrict__ stim,
                             float* __restrict__ h_out,
                             float* __restrict__ W_out,
                             int n_pairs)
{
    __shared__ float  wsh[WPB][NB * STRIDE];
    __shared__ float4 hsh[WPB][NB];

    const int warp = threadIdx.x >> 5;
    const int lane = threadIdx.x & 31;
    const int pair = blockIdx.x * WPB + warp;
    if (pair >= n_pairs) return;

    const float* Wp = W + (size_t)pair * (NB * NB);
    float*  ws = wsh[warp];
    float4* hs = hsh[warp];

    const int qr = lane >> 3;        // quarter-warp: which of 4 rows this step
    const int qc = (lane & 7) * 4;   // float4 column offset within row

    // ---- W tile: global -> shared, 4 rows (512B contiguous) per LDG.128 step ----
    #pragma unroll
    for (int t = 0; t < 8; ++t) {
        const int r = t * 4 + qr;
        const float4 v = *(const float4*)(Wp + r * NB + qc);
        *(float4*)(ws + r * STRIDE + qc) = v;
    }

    // ---- h row: one float4 per lane; stage in shared for broadcast reads ----
    const float4 hv = ((const float4*)(h + (size_t)pair * NB * 4))[lane];
    hs[lane] = hv;
    const float s = stim[(size_t)pair * NB + lane];
    __syncwarp();

    // ---- own W row into registers (8 conflict-free LDS.128) ----
    float4 w4[8];
    #pragma unroll
    for (int t = 0; t < 8; ++t)
        w4[t] = *(const float4*)(ws + lane * STRIDE + t * 4);

    // ---- masked matvec: 1 LDS.128 broadcast per j ----
    float ifx = 0.f, ify = 0.f, ifz = 0.f, ifw = 0.f, wsum = 0.f;
    #pragma unroll
    for (int t = 0; t < 8; ++t) {
        const float wq[4] = {w4[t].x, w4[t].y, w4[t].z, w4[t].w};
        #pragma unroll
        for (int e = 0; e < 4; ++e) {
            const int j = t * 4 + e;
            const float wij = (j == lane) ? 0.0f : wq[e];
            const float4 hj = hs[j];
            ifx += wij * hj.x;
            ify += wij * hj.y;
            ifz += wij * hj.z;
            ifw += wij * hj.w;
            wsum += wij;
        }
    }
    const float inv = 1.0f / (wsum + 1e-8f);
    const float En = ifx * inv, Pn = ify * inv, Gn = ifz * inv, Ln = ifw * inv;

    // ---- channel update ----
    const float E = hv.x, P = hv.y, G = hv.z, L = hv.w;
    const float E_new = clamp01(E + 0.3f * s - 0.4f * P - 0.2f * G);
    const float P_new = clamp01(P + 0.5f * s + 0.3f * (Pn - P) - 0.2f * E);
    const float G_new = clamp01(G + 0.4f * E * (1.0f - P) + 0.2f * (Gn - G) - 0.3f * P);
    const float good  = 0.5f * En + 0.5f * Gn;
    const float L_new = clamp01(L + 0.4f * good + 0.3f * (Ln - L) - 0.3f * P);

    const float4 hn = make_float4(E_new, P_new, G_new, L_new);
    ((float4*)(h_out + (size_t)pair * NB * 4))[lane] = hn;

    // ---- publish h_new for broadcast (all matvec reads of hs are done) ----
    __syncwarp();
    hs[lane] = hn;
    __syncwarp();

    // ---- W update in registers; 1 LDS.128 broadcast per j ----
    #pragma unroll
    for (int t = 0; t < 8; ++t) {
        float wq[4] = {w4[t].x, w4[t].y, w4[t].z, w4[t].w};
        #pragma unroll
        for (int e = 0; e < 4; ++e) {
            const int j = t * 4 + e;
            const float4 hj = hs[j];
            const float dx = hn.x - hj.x, dy = hn.y - hj.y;
            const float dz = hn.z - hj.z, dw = hn.w - hj.w;
            const float sq = dx * dx + dy * dy + dz * dz + dw * dw;
            const float dist = (sq > 0.0f) ? sq * rsqrtf(sq) : 0.0f;
            float wn = 0.95f * wq[e] + 0.05f * (hn.w + hj.w) * dist;
            wn = clamp01(wn);
            if (j == lane) wn = 0.0f;
            wq[e] = wn;
        }
        w4[t] = make_float4(wq[0], wq[1], wq[2], wq[3]);
    }

    // ---- write row back to shared (conflict-free), then coalesced STG.128 ----
    #pragma unroll
    for (int t = 0; t < 8; ++t)
        *(float4*)(ws + lane * STRIDE + t * 4) = w4[t];
    __syncwarp();

    float* Wo = W_out + (size_t)pair * (NB * NB);
    #pragma unroll
    for (int t = 0; t < 8; ++t) {
        const int r = t * 4 + qr;
        const float4 v = *(const float4*)(ws + r * STRIDE + qc);
        *(float4*)(Wo + r * NB + qc) = v;
    }
}

extern "C" void kernel_launch(void* const* d_in, const int* in_sizes, int n_in,
                              void* d_out, int out_size) {
    const float* h    = (const float*)d_in[0];  // [B,S,32,4]
    const float* W    = (const float*)d_in[1];  // [B,S,32,32]
    const float* stim = (const float*)d_in[2];  // [B,S,32]

    const int n_pairs = in_sizes[2] / NB;       // B*S

    float* h_out = (float*)d_out;                       // h_new first
    float* W_out = (float*)d_out + (size_t)in_sizes[0]; // then W_new

    const int blocks = (n_pairs + WPB - 1) / WPB;
    BioTokenMucusSim_kernel<<<blocks, THREADS>>>(h, W, stim, h_out, W_out, n_pairs);
}

// round 3
// speedup vs baseline: 1.2871x; 1.1539x over previous
#include <cuda_runtime.h>
#include <cuda_bf16.h>

#define NB 32
#define WPB 8
#define THREADS (WPB * 32)
#define STRIDE 36   // float4-aligned padded row; all patterns at smem wavefront floor

__device__ __forceinline__ float clamp01(float x) {
    return fminf(fmaxf(x, 0.0f), 1.0f);
}

__global__ __launch_bounds__(THREADS, 5)
void BioTokenMucusSim_kernel(const float* __restrict__ h,
                             const float* __restrict__ W,
                             const float* __restrict__ stim,
                             float* __restrict__ h_out,
                             float* __restrict__ W_out,
                             int n_pairs)
{
    __shared__ float  wsh[WPB][NB * STRIDE];
    __shared__ float4 hsh[WPB][NB];

    const int warp = threadIdx.x >> 5;
    const int lane = threadIdx.x & 31;
    const int pair = blockIdx.x * WPB + warp;
    if (pair >= n_pairs) return;

    const float* Wp = W + (size_t)pair * (NB * NB);
    float*  ws = wsh[warp];
    float4* hs = hsh[warp];

    const int qr = lane >> 3;        // row-within-group for 4-row load steps
    const int qc = (lane & 7) * 4;   // float4 column offset

    // ---- front-batched loads: 8x LDG.128 (W) + h float4 + stim (MLP ~10) ----
    float4 wtmp[8];
    #pragma unroll
    for (int t = 0; t < 8; ++t)
        wtmp[t] = *(const float4*)(Wp + (t * 4 + qr) * NB + qc);
    const float4 hv = ((const float4*)(h + (size_t)pair * NB * 4))[lane];
    const float s = stim[(size_t)pair * NB + lane];

    #pragma unroll
    for (int t = 0; t < 8; ++t)
        *(float4*)(ws + (t * 4 + qr) * STRIDE + qc) = wtmp[t];
    hs[lane] = hv;
    __syncwarp();

    // ---- masked matvec: row chunks consumed straight from shared ----
    float ifx = 0.f, ify = 0.f, ifz = 0.f, ifw = 0.f, wsum = 0.f;
    #pragma unroll
    for (int t = 0; t < 8; ++t) {
        const float4 w4 = *(const float4*)(ws + lane * STRIDE + t * 4);
        const float wq[4] = {w4.x, w4.y, w4.z, w4.w};
        #pragma unroll
        for (int e = 0; e < 4; ++e) {
            const int j = t * 4 + e;
            const float wij = (j == lane) ? 0.0f : wq[e];
            const float4 hj = hs[j];            // broadcast: 1 wavefront
            ifx += wij * hj.x;
            ify += wij * hj.y;
            ifz += wij * hj.z;
            ifw += wij * hj.w;
            wsum += wij;
        }
    }
    const float inv = 1.0f / (wsum + 1e-8f);
    const float En = ifx * inv, Pn = ify * inv, Gn = ifz * inv, Ln = ifw * inv;

    // ---- channel update ----
    const float E = hv.x, P = hv.y, G = hv.z, L = hv.w;
    const float E_new = clamp01(E + 0.3f * s - 0.4f * P - 0.2f * G);
    const float P_new = clamp01(P + 0.5f * s + 0.3f * (Pn - P) - 0.2f * E);
    const float G_new = clamp01(G + 0.4f * E * (1.0f - P) + 0.2f * (Gn - G) - 0.3f * P);
    const float good  = 0.5f * En + 0.5f * Gn;
    const float L_new = clamp01(L + 0.4f * good + 0.3f * (Ln - L) - 0.3f * P);

    const float4 hn = make_float4(E_new, P_new, G_new, L_new);
    ((float4*)(h_out + (size_t)pair * NB * 4))[lane] = hn;

    __syncwarp();                   // matvec reads of hs done
    hs[lane] = hn;                  // publish h_new
    __syncwarp();

    // ---- fused W-update + coalesced store (original W read in store pattern) ----
    float4 hj[4];
    #pragma unroll
    for (int e = 0; e < 4; ++e)
        hj[e] = hs[qc + e];          // hoisted: invariant across t

    float* Wo = W_out + (size_t)pair * (NB * NB);
    #pragma unroll
    for (int t = 0; t < 8; ++t) {
        const int r = t * 4 + qr;
        const float4 w  = *(const float4*)(ws + r * STRIDE + qc);
        const float4 hr = hs[r];
        const float wq[4] = {w.x, w.y, w.z, w.w};
        float out[4];
        #pragma unroll
        for (int e = 0; e < 4; ++e) {
            const float dx = hr.x - hj[e].x, dy = hr.y - hj[e].y;
            const float dz = hr.z - hj[e].z, dw = hr.w - hj[e].w;
            const float sq = dx * dx + dy * dy + dz * dz + dw * dw;
            const float dist = (sq > 0.0f) ? sq * rsqrtf(sq) : 0.0f;
            // W_new = 0.95*W + 0.05*(L_i+L_j)*dist, clipped, diag zeroed
            float wn = 0.95f * wq[e] + 0.05f * (hr.w + hj[e].w) * dist;
            wn = clamp01(wn);
            if (r == qc + e) wn = 0.0f;
            out[e] = wn;
        }
        *(float4*)(Wo + r * NB + qc) = make_float4(out[0], out[1], out[2], out[3]);
    }
}

extern "C" void kernel_launch(void* const* d_in, const int* in_sizes, int n_in,
                              void* d_out, int out_size) {
    const float* h    = (const float*)d_in[0];  // [B,S,32,4]
    const float* W    = (const float*)d_in[1];  // [B,S,32,32]
    const float* stim = (const float*)d_in[2];  // [B,S,32]

    const int n_pairs = in_sizes[2] / NB;       // B*S

    float* h_out = (float*)d_out;                       // h_new first
    float* W_out = (float*)d_out + (size_t)in_sizes[0]; // then W_new

    const int blocks = (n_pairs + WPB - 1) / WPB;
    BioTokenMucusSim_kernel<<<blocks, THREADS>>>(h, W, stim, h_out, W_out, n_pairs);
}

// round 4
// speedup vs baseline: 1.2953x; 1.0063x over previous
#include <cuda_runtime.h>
#include <cuda_bf16.h>

#define NB 32
#define WPB 8
#define THREADS (WPB * 32)
#define STRIDE 36   // padded row; pad floats [32..35] of row j hold h[j] (overlay)

__device__ __forceinline__ float clamp01(float x) {
    return fminf(fmaxf(x, 0.0f), 1.0f);
}

__global__ __launch_bounds__(THREADS, 6)
void BioTokenMucusSim_kernel(const float* __restrict__ h,
                             const float* __restrict__ W,
                             const float* __restrict__ stim,
                             float* __restrict__ h_out,
                             float* __restrict__ W_out,
                             int n_pairs)
{
    // 8 warps x 32 rows x 36 floats = 36864 B/block -> 6 blocks/SM by smem
    __shared__ float wsh[WPB][NB * STRIDE];

    const int warp = threadIdx.x >> 5;
    const int lane = threadIdx.x & 31;
    const int pair = blockIdx.x * WPB + warp;
    if (pair >= n_pairs) return;

    const float* Wp = W + (size_t)pair * (NB * NB);
    float* ws = wsh[warp];

    const int qr = lane >> 3;        // row-in-group
    const int qc = (lane & 7) * 4;   // float4 col offset

    // ---- stage W tile in two rounds of 4 LDG.128 (lower peak regs) ----
    #pragma unroll
    for (int half = 0; half < 2; ++half) {
        float4 tmp[4];
        #pragma unroll
        for (int t = 0; t < 4; ++t)
            tmp[t] = *(const float4*)(Wp + ((half * 4 + t) * 4 + qr) * NB + qc);
        #pragma unroll
        for (int t = 0; t < 4; ++t)
            *(float4*)(ws + ((half * 4 + t) * 4 + qr) * STRIDE + qc) = tmp[t];
    }

    // ---- h into row padding; zero W diagonal in shared (update forces it 0) ----
    const float4 hv = ((const float4*)(h + (size_t)pair * NB * 4))[lane];
    const float s = stim[(size_t)pair * NB + lane];
    *(float4*)(ws + lane * STRIDE + 32) = hv;     // hs[lane] overlay
    __syncwarp();
    ws[lane * STRIDE + lane] = 0.0f;              // diag := 0 (conflict-free)
    __syncwarp();

    // ---- masked matvec: no per-j select needed (diag already 0) ----
    float ifx = 0.f, ify = 0.f, ifz = 0.f, ifw = 0.f, wsum = 0.f;
    #pragma unroll
    for (int t = 0; t < 8; ++t) {
        const float4 w4 = *(const float4*)(ws + lane * STRIDE + t * 4);
        const float wq[4] = {w4.x, w4.y, w4.z, w4.w};
        #pragma unroll
        for (int e = 0; e < 4; ++e) {
            const int j = t * 4 + e;
            const float4 hj = *(const float4*)(ws + j * STRIDE + 32); // bcast 1wf
            ifx  += wq[e] * hj.x;
            ify  += wq[e] * hj.y;
            ifz  += wq[e] * hj.z;
            ifw  += wq[e] * hj.w;
            wsum += wq[e];
        }
    }
    const float inv = 1.0f / (wsum + 1e-8f);
    const float En = ifx * inv, Pn = ify * inv, Gn = ifz * inv, Ln = ifw * inv;

    // ---- channel update ----
    const float E = hv.x, P = hv.y, G = hv.z, L = hv.w;
    const float E_new = clamp01(E + 0.3f * s - 0.4f * P - 0.2f * G);
    const float P_new = clamp01(P + 0.5f * s + 0.3f * (Pn - P) - 0.2f * E);
    const float G_new = clamp01(G + 0.4f * E * (1.0f - P) + 0.2f * (Gn - G) - 0.3f * P);
    const float good  = 0.5f * En + 0.5f * Gn;
    const float L_new = clamp01(L + 0.4f * good + 0.3f * (Ln - L) - 0.3f * P);

    const float4 hn = make_float4(E_new, P_new, G_new, L_new);
    ((float4*)(h_out + (size_t)pair * NB * 4))[lane] = hn;

    __syncwarp();                                  // matvec h reads done
    *(float4*)(ws + lane * STRIDE + 32) = hn;      // publish h_new
    __syncwarp();

    // ---- fused W-update + coalesced store (reads W tile in store pattern) ----
    float4 hj4[4];
    #pragma unroll
    for (int e = 0; e < 4; ++e)
        hj4[e] = *(const float4*)(ws + (qc + e) * STRIDE + 32);

    float* Wo = W_out + (size_t)pair * (NB * NB);
    #pragma unroll
    for (int t = 0; t < 8; ++t) {
        const int r = t * 4 + qr;
        const float4 w  = *(const float4*)(ws + r * STRIDE + qc);
        const float4 hr = *(const float4*)(ws + r * STRIDE + 32);  // 4 addrs, 1wf
        const float wq[4] = {w.x, w.y, w.z, w.w};
        float out[4];
        #pragma unroll
        for (int e = 0; e < 4; ++e) {
            const float dx = hr.x - hj4[e].x, dy = hr.y - hj4[e].y;
            const float dz = hr.z - hj4[e].z, dw = hr.w - hj4[e].w;
            const float sq = dx * dx + dy * dy + dz * dz + dw * dw;
            const float dist = (sq > 0.0f) ? sq * rsqrtf(sq) : 0.0f;
            float wn = 0.95f * wq[e] + 0.05f * (hr.w + hj4[e].w) * dist;
            wn = clamp01(wn);
            if (r == qc + e) wn = 0.0f;            // diagonal
            out[e] = wn;
        }
        *(float4*)(Wo + r * NB + qc) = make_float4(out[0], out[1], out[2], out[3]);
    }
}

extern "C" void kernel_launch(void* const* d_in, const int* in_sizes, int n_in,
                              void* d_out, int out_size) {
    const float* h    = (const float*)d_in[0];  // [B,S,32,4]
    const float* W    = (const float*)d_in[1];  // [B,S,32,32]
    const float* stim = (const float*)d_in[2];  // [B,S,32]

    const int n_pairs = in_sizes[2] / NB;       // B*S

    float* h_out = (float*)d_out;                       // h_new first
    float* W_out = (float*)d_out + (size_t)in_sizes[0]; // then W_new

    const int blocks = (n_pairs + WPB - 1) / WPB;
    BioTokenMucusSim_kernel<<<blocks, THREADS>>>(h, W, stim, h_out, W_out, n_pairs);
}

// round 5
// speedup vs baseline: 1.3083x; 1.0101x over previous
#include <cuda_runtime.h>
#include <cuda_bf16.h>

#define NB 32
#define WPB 8
#define THREADS (WPB * 32)
#define STRIDE 36   // padded row; floats [32..35] of row j hold h[j] (overlay)

__device__ __forceinline__ float clamp01(float x) {
    return fminf(fmaxf(x, 0.0f), 1.0f);
}

__device__ __forceinline__ void cp_async16(void* smem_dst, const void* gmem_src) {
    unsigned sa = (unsigned)__cvta_generic_to_shared(smem_dst);
    asm volatile("cp.async.cg.shared.global [%0], [%1], 16;\n"
                 :: "r"(sa), "l"(gmem_src) : "memory");
}

__global__ __launch_bounds__(THREADS, 6)
void BioTokenMucusSim_kernel(const float* __restrict__ h,
                             const float* __restrict__ W,
                             const float* __restrict__ stim,
                             float* __restrict__ h_out,
                             float* __restrict__ W_out,
                             int n_pairs)
{
    // 8 warps x 32 rows x 36 floats = 36864 B/block -> 6 blocks/SM
    __shared__ float wsh[WPB][NB * STRIDE];

    const int warp = threadIdx.x >> 5;
    const int lane = threadIdx.x & 31;
    const int pair = blockIdx.x * WPB + warp;
    if (pair >= n_pairs) return;

    const float* Wp = W + (size_t)pair * (NB * NB);
    float* ws = wsh[warp];

    const int qr = lane >> 3;        // row-in-group
    const int qc = (lane & 7) * 4;   // float4 col offset

    // ---- W tile + h: direct global->shared via cp.async (no reg staging) ----
    #pragma unroll
    for (int t = 0; t < 8; ++t) {
        const int r = t * 4 + qr;
        cp_async16(ws + r * STRIDE + qc, Wp + r * NB + qc);
    }
    cp_async16(ws + lane * STRIDE + 32, h + (size_t)pair * NB * 4 + lane * 4);
    asm volatile("cp.async.commit_group;\n" ::: "memory");

    const float s = stim[(size_t)pair * NB + lane];   // overlap with copies

    asm volatile("cp.async.wait_group 0;\n" ::: "memory");
    __syncwarp();

    // diag := 0 (update forces it 0 anyway); read own h back (disjoint addrs)
    ws[lane * STRIDE + lane] = 0.0f;
    const float4 hv = *(const float4*)(ws + lane * STRIDE + 32);
    __syncwarp();

    // ---- masked matvec: row from shared, h via 1-wf broadcasts ----
    float ifx = 0.f, ify = 0.f, ifz = 0.f, ifw = 0.f, wsum = 0.f;
    #pragma unroll
    for (int t = 0; t < 8; ++t) {
        const float4 w4 = *(const float4*)(ws + lane * STRIDE + t * 4);
        const float wq[4] = {w4.x, w4.y, w4.z, w4.w};
        #pragma unroll
        for (int e = 0; e < 4; ++e) {
            const int j = t * 4 + e;
            const float4 hj = *(const float4*)(ws + j * STRIDE + 32);
            ifx  += wq[e] * hj.x;
            ify  += wq[e] * hj.y;
            ifz  += wq[e] * hj.z;
            ifw  += wq[e] * hj.w;
            wsum += wq[e];
        }
    }
    const float inv = 1.0f / (wsum + 1e-8f);
    const float En = ifx * inv, Pn = ify * inv, Gn = ifz * inv, Ln = ifw * inv;

    // ---- channel update ----
    const float E = hv.x, P = hv.y, G = hv.z, L = hv.w;
    const float E_new = clamp01(E + 0.3f * s - 0.4f * P - 0.2f * G);
    const float P_new = clamp01(P + 0.5f * s + 0.3f * (Pn - P) - 0.2f * E);
    const float G_new = clamp01(G + 0.4f * E * (1.0f - P) + 0.2f * (Gn - G) - 0.3f * P);
    const float good  = 0.5f * En + 0.5f * Gn;
    const float L_new = clamp01(L + 0.4f * good + 0.3f * (Ln - L) - 0.3f * P);

    const float4 hn = make_float4(E_new, P_new, G_new, L_new);
    ((float4*)(h_out + (size_t)pair * NB * 4))[lane] = hn;

    __syncwarp();                                  // matvec h reads done
    *(float4*)(ws + lane * STRIDE + 32) = hn;      // publish h_new
    __syncwarp();

    // ---- fused W-update + coalesced store (reads W tile in store pattern) ----
    float4 hj4[4];
    #pragma unroll
    for (int e = 0; e < 4; ++e)
        hj4[e] = *(const float4*)(ws + (qc + e) * STRIDE + 32);

    float* Wo = W_out + (size_t)pair * (NB * NB);
    #pragma unroll
    for (int t = 0; t < 8; ++t) {
        const int r = t * 4 + qr;
        const float4 w  = *(const float4*)(ws + r * STRIDE + qc);
        const float4 hr = *(const float4*)(ws + r * STRIDE + 32);  // 1 wf
        const float wq[4] = {w.x, w.y, w.z, w.w};
        float out[4];
        #pragma unroll
        for (int e = 0; e < 4; ++e) {
            const float dx = hr.x - hj4[e].x, dy = hr.y - hj4[e].y;
            const float dz = hr.z - hj4[e].z, dw = hr.w - hj4[e].w;
            const float sq = dx * dx + dy * dy + dz * dz + dw * dw;
            const float dist = (sq > 0.0f) ? sq * rsqrtf(sq) : 0.0f;
            float wn = 0.95f * wq[e] + 0.05f * (hr.w + hj4[e].w) * dist;
            wn = clamp01(wn);
            if (r == qc + e) wn = 0.0f;            // diagonal
            out[e] = wn;
        }
        *(float4*)(Wo + r * NB + qc) = make_float4(out[0], out[1], out[2], out[3]);
    }
}

extern "C" void kernel_launch(void* const* d_in, const int* in_sizes, int n_in,
                              void* d_out, int out_size) {
    const float* h    = (const float*)d_in[0];  // [B,S,32,4]
    const float* W    = (const float*)d_in[1];  // [B,S,32,32]
    const float* stim = (const float*)d_in[2];  // [B,S,32]

    const int n_pairs = in_sizes[2] / NB;       // B*S

    float* h_out = (float*)d_out;                       // h_new first
    float* W_out = (float*)d_out + (size_t)in_sizes[0]; // then W_new

    const int blocks = (n_pairs + WPB - 1) / WPB;
    BioTokenMucusSim_kernel<<<blocks, THREADS>>>(h, W, stim, h_out, W_out, n_pairs);
}